// round 2
// baseline (speedup 1.0000x reference)
#include <cuda_runtime.h>

#define DDIM   64
#define KCODES 2048
#define NPTS   32768      // 32 * 32 * 32
#define HW     1024       // 32 * 32
#define TM     128        // points per block tile
#define TK     64         // codes per smem tile

__device__ int   g_idx[NPTS];
__device__ float g_esq[KCODES];

// ---------------------------------------------------------------------------
// Kernel 1: e_sq[k] = sum_d codebook[k][d]^2  (sequential fp32, matches ref order)
// ---------------------------------------------------------------------------
__global__ void esq_kernel(const float* __restrict__ cb) {
    int k = blockIdx.x * blockDim.x + threadIdx.x;
    if (k < KCODES) {
        float s = 0.f;
        const float* row = cb + k * DDIM;
        #pragma unroll
        for (int d = 0; d < DDIM; ++d) s = fmaf(row[d], row[d], s);
        g_esq[k] = s;
    }
}

// ---------------------------------------------------------------------------
// Kernel 2: main distance + argmin.
// Block = 128 points x all 2048 codes. 256 threads: col = tid&31 (4 points
// each), row = tid>>5 (8 codes each per 64-code tile). Register tile 4x8.
// Argmin key: (ordered-float(dist) << 32) | code  -> min() == first-index
// tie-break, exactly like jnp.argmin.
// ---------------------------------------------------------------------------
__global__ __launch_bounds__(256)
void vq_main(const float* __restrict__ laten,
             const float* __restrict__ cb,
             float* __restrict__ out) {
    __shared__ float xs[DDIM][TM];   // 32 KB, [d][point]
    __shared__ float es[TK][DDIM];   // 16 KB, [code][d] (row-major copy of cb tile)

    const int tid = threadIdx.x;
    const int col = tid & 31;        // point group (4 points)
    const int row = tid >> 5;        // code group (8 codes)

    const int p0  = blockIdx.x * TM;           // tile stays within one batch (128 | 1024)
    const int b   = p0 >> 10;
    const int hw0 = p0 & 1023;
    const float* lat_b = laten + (size_t)b * (DDIM * HW) + hw0;

    // stage x tile: coalesced global rows, conflict-free STS
    #pragma unroll
    for (int it = 0; it < (DDIM * TM) / 256; ++it) {
        int idx = tid + it * 256;
        int d = idx >> 7, p = idx & 127;
        xs[d][p] = lat_b[d * HW + p];
    }
    __syncthreads();

    // x_sq for my 4 points (sequential over d, like jnp.sum)
    float xsq0 = 0.f, xsq1 = 0.f, xsq2 = 0.f, xsq3 = 0.f;
    #pragma unroll
    for (int d = 0; d < DDIM; ++d) {
        float4 xv = *reinterpret_cast<const float4*>(&xs[d][4 * col]);
        xsq0 = fmaf(xv.x, xv.x, xsq0);
        xsq1 = fmaf(xv.y, xv.y, xsq1);
        xsq2 = fmaf(xv.z, xv.z, xsq2);
        xsq3 = fmaf(xv.w, xv.w, xsq3);
    }

    unsigned long long key[4] = {~0ULL, ~0ULL, ~0ULL, ~0ULL};

    for (int kt = 0; kt < KCODES / TK; ++kt) {
        __syncthreads();   // previous tile's es reads done
        {
            const float* src = cb + (size_t)kt * TK * DDIM;  // fully contiguous
            float* esf = &es[0][0];
            #pragma unroll
            for (int it = 0; it < (TK * DDIM) / 256; ++it)
                esf[tid + it * 256] = src[tid + it * 256];
        }
        __syncthreads();

        float acc[8][4];
        #pragma unroll
        for (int cc = 0; cc < 8; ++cc) {
            acc[cc][0] = 0.f; acc[cc][1] = 0.f; acc[cc][2] = 0.f; acc[cc][3] = 0.f;
        }

        #pragma unroll 4
        for (int d = 0; d < DDIM; ++d) {
            float4 xv = *reinterpret_cast<const float4*>(&xs[d][4 * col]);
            #pragma unroll
            for (int cc = 0; cc < 8; ++cc) {
                float ev = es[row * 8 + cc][d];   // warp-uniform -> LDS broadcast
                acc[cc][0] = fmaf(xv.x, ev, acc[cc][0]);
                acc[cc][1] = fmaf(xv.y, ev, acc[cc][1]);
                acc[cc][2] = fmaf(xv.z, ev, acc[cc][2]);
                acc[cc][3] = fmaf(xv.w, ev, acc[cc][3]);
            }
        }

        #pragma unroll
        for (int cc = 0; cc < 8; ++cc) {
            int code = kt * TK + row * 8 + cc;
            float eq = __ldg(&g_esq[code]);
            #pragma unroll
            for (int pp = 0; pp < 4; ++pp) {
                float xq = (pp == 0) ? xsq0 : (pp == 1) ? xsq1 : (pp == 2) ? xsq2 : xsq3;
                float dist = fmaf(-2.f, acc[cc][pp], xq) + eq;  // (x^2 - 2x.e) + e^2
                unsigned int u = __float_as_uint(dist);
                u = (u & 0x80000000u) ? ~u : (u | 0x80000000u); // total order encode
                unsigned long long kk = ((unsigned long long)u << 32) | (unsigned)code;
                if (kk < key[pp]) key[pp] = kk;
            }
        }
    }

    // cross-row reduction: reuse xs as u64 red[8][TM]
    __syncthreads();
    unsigned long long* red = reinterpret_cast<unsigned long long*>(&xs[0][0]);
    #pragma unroll
    for (int pp = 0; pp < 4; ++pp)
        red[row * TM + 4 * col + pp] = key[pp];
    __syncthreads();

    if (tid < TM) {
        unsigned long long kmin = red[tid];
        #pragma unroll
        for (int r = 1; r < 8; ++r) {
            unsigned long long k2 = red[r * TM + tid];
            if (k2 < kmin) kmin = k2;
        }
        int code = (int)(kmin & 0xFFFFFFFFULL);
        g_idx[p0 + tid] = code;
        out[p0 + tid]   = (float)code;   // output #1: closest_idx (b,h,w) order
    }
}

// ---------------------------------------------------------------------------
// Kernel 3: quant_laten gather, output layout (B, D, H, W) after the idx block
// ---------------------------------------------------------------------------
__global__ void gather_kernel(const float* __restrict__ cb, float* __restrict__ out) {
    int i = blockIdx.x * blockDim.x + threadIdx.x;
    if (i < 32 * DDIM * HW) {
        int hw = i & 1023;
        int d  = (i >> 10) & 63;
        int b  = i >> 16;
        int k  = g_idx[(b << 10) | hw];
        out[NPTS + i] = cb[k * DDIM + d];
    }
}

extern "C" void kernel_launch(void* const* d_in, const int* in_sizes, int n_in,
                              void* d_out, int out_size) {
    const float* laten = (const float*)d_in[0];   // (32, 64, 32, 32) f32
    const float* cb    = (const float*)d_in[1];   // (2048, 64) f32
    float* out = (float*)d_out;                   // [32768 idx | 2097152 quant]

    esq_kernel<<<KCODES / 256, 256>>>(cb);
    vq_main<<<NPTS / TM, 256>>>(laten, cb, out);
    gather_kernel<<<(32 * DDIM * HW) / 256, 256>>>(cb, out);
}

// round 3
// speedup vs baseline: 1.0220x; 1.0220x over previous
#include <cuda_runtime.h>

#define DDIM   64
#define KCODES 2048
#define NPTS   32768      // 32 * 32 * 32
#define HW     1024       // 32 * 32
#define TM     256        // points per block tile
#define TK     64         // codes per smem tile
#define NSPLIT 8
#define KSPL   (KCODES / NSPLIT)   // 256 codes per split

__device__ int                g_idx[NPTS];
__device__ float              g_esq[KCODES];
__device__ unsigned long long g_part[NSPLIT * NPTS];

// ---- f32x2 helpers (FFMA2 only reachable via PTX) ------------------------
__device__ __forceinline__ unsigned long long fma2(unsigned long long a,
                                                   unsigned long long b,
                                                   unsigned long long c) {
    unsigned long long d;
    asm("fma.rn.f32x2 %0, %1, %2, %3;" : "=l"(d) : "l"(a), "l"(b), "l"(c));
    return d;
}
__device__ __forceinline__ unsigned long long rep2(float x) {
    unsigned long long d;
    asm("mov.b64 %0, {%1, %1};" : "=l"(d) : "f"(x), "f"(x));
    return d;
}
__device__ __forceinline__ void unpack2(unsigned long long v, float& lo, float& hi) {
    asm("mov.b64 {%0, %1}, %2;" : "=f"(lo), "=f"(hi) : "l"(v));
}
__device__ __forceinline__ unsigned long long enc_key(float dist, int code) {
    unsigned int u = __float_as_uint(dist);
    u = (u & 0x80000000u) ? ~u : (u | 0x80000000u);  // total order
    return ((unsigned long long)u << 32) | (unsigned)code;
}

union F4U { float4 f; unsigned long long u[2]; };

// ---------------------------------------------------------------------------
// Kernel 1: e_sq[k] (sequential fp32 order preserved, float4 loads)
// ---------------------------------------------------------------------------
__global__ void esq_kernel(const float* __restrict__ cb) {
    int k = blockIdx.x * blockDim.x + threadIdx.x;
    if (k < KCODES) {
        const float4* r = reinterpret_cast<const float4*>(cb + (size_t)k * DDIM);
        float s = 0.f;
        #pragma unroll
        for (int i = 0; i < 16; ++i) {
            float4 v = r[i];
            s = fmaf(v.x, v.x, s); s = fmaf(v.y, v.y, s);
            s = fmaf(v.z, v.z, s); s = fmaf(v.w, v.w, s);
        }
        g_esq[k] = s;
    }
}

// ---------------------------------------------------------------------------
// Kernel 2: main distance + per-split argmin.
// Grid (NSPLIT, NPTS/TM). Block 256 thr = 32 cols (8 pts) x 8 rows (codes).
// FFMA2 register tile 8 pts x 8 codes, d unrolled x2 with LDS.64 ev.
// ---------------------------------------------------------------------------
__global__ __launch_bounds__(256, 2)
void vq_main(const float* __restrict__ laten, const float* __restrict__ cb) {
    extern __shared__ float sm[];
    float (*xs)[TM]   = reinterpret_cast<float (*)[TM]>(sm);              // 64 KB
    float (*es)[DDIM] = reinterpret_cast<float (*)[DDIM]>(sm + DDIM * TM); // 16 KB

    const int tid   = threadIdx.x;
    const int col   = tid & 31;
    const int row   = tid >> 5;
    const int split = blockIdx.x;
    const int p0    = blockIdx.y * TM;
    const int b     = p0 >> 10;
    const int hw0   = p0 & 1023;
    const float* lat_b = laten + (size_t)b * (DDIM * HW) + hw0;

    // stage x tile (float4, coalesced)
    #pragma unroll
    for (int it = 0; it < 16; ++it) {
        int f = tid + it * 256;               // 4096 float4s
        int d = f >> 6, pf = f & 63;
        float4 v = *reinterpret_cast<const float4*>(lat_b + d * HW + pf * 4);
        *reinterpret_cast<float4*>(&xs[d][pf * 4]) = v;
    }
    __syncthreads();

    // x_sq for my 8 points, sequential over d
    float xsq[8];
    #pragma unroll
    for (int j = 0; j < 8; ++j) xsq[j] = 0.f;
    #pragma unroll 8
    for (int d = 0; d < DDIM; ++d) {
        float4 a = *reinterpret_cast<const float4*>(&xs[d][8 * col]);
        float4 c = *reinterpret_cast<const float4*>(&xs[d][8 * col + 4]);
        xsq[0] = fmaf(a.x, a.x, xsq[0]); xsq[1] = fmaf(a.y, a.y, xsq[1]);
        xsq[2] = fmaf(a.z, a.z, xsq[2]); xsq[3] = fmaf(a.w, a.w, xsq[3]);
        xsq[4] = fmaf(c.x, c.x, xsq[4]); xsq[5] = fmaf(c.y, c.y, xsq[5]);
        xsq[6] = fmaf(c.z, c.z, xsq[6]); xsq[7] = fmaf(c.w, c.w, xsq[7]);
    }

    unsigned long long key[8];
    #pragma unroll
    for (int j = 0; j < 8; ++j) key[j] = ~0ULL;

    for (int kt = 0; kt < KSPL / TK; ++kt) {
        __syncthreads();
        {   // stage 64-code tile (contiguous)
            const float4* src = reinterpret_cast<const float4*>(
                cb + ((size_t)split * KSPL + kt * TK) * DDIM);
            float4* dst = reinterpret_cast<float4*>(&es[0][0]);
            #pragma unroll
            for (int it = 0; it < 4; ++it) dst[tid + it * 256] = src[tid + it * 256];
        }
        __syncthreads();

        unsigned long long acc[8][4];
        #pragma unroll
        for (int cc = 0; cc < 8; ++cc)
            #pragma unroll
            for (int q = 0; q < 4; ++q) acc[cc][q] = 0ULL;

        #pragma unroll 2
        for (int d = 0; d < DDIM; d += 2) {
            F4U A0, A1, B0, B1;
            A0.f = *reinterpret_cast<const float4*>(&xs[d][8 * col]);
            A1.f = *reinterpret_cast<const float4*>(&xs[d][8 * col + 4]);
            B0.f = *reinterpret_cast<const float4*>(&xs[d + 1][8 * col]);
            B1.f = *reinterpret_cast<const float4*>(&xs[d + 1][8 * col + 4]);
            #pragma unroll
            for (int cc = 0; cc < 8; ++cc) {
                float2 e = *reinterpret_cast<const float2*>(&es[row * 8 + cc][d]);
                unsigned long long e0 = rep2(e.x);
                unsigned long long e1 = rep2(e.y);
                acc[cc][0] = fma2(A0.u[0], e0, acc[cc][0]);
                acc[cc][1] = fma2(A0.u[1], e0, acc[cc][1]);
                acc[cc][2] = fma2(A1.u[0], e0, acc[cc][2]);
                acc[cc][3] = fma2(A1.u[1], e0, acc[cc][3]);
                acc[cc][0] = fma2(B0.u[0], e1, acc[cc][0]);
                acc[cc][1] = fma2(B0.u[1], e1, acc[cc][1]);
                acc[cc][2] = fma2(B1.u[0], e1, acc[cc][2]);
                acc[cc][3] = fma2(B1.u[1], e1, acc[cc][3]);
            }
        }

        #pragma unroll
        for (int cc = 0; cc < 8; ++cc) {
            int code = split * KSPL + kt * TK + row * 8 + cc;
            float eq = __ldg(&g_esq[code]);
            #pragma unroll
            for (int q = 0; q < 4; ++q) {
                float dlo, dhi;
                unpack2(acc[cc][q], dlo, dhi);
                float dist0 = fmaf(-2.f, dlo, xsq[2 * q])     + eq;
                float dist1 = fmaf(-2.f, dhi, xsq[2 * q + 1]) + eq;
                unsigned long long k0 = enc_key(dist0, code);
                unsigned long long k1 = enc_key(dist1, code);
                if (k0 < key[2 * q])     key[2 * q]     = k0;
                if (k1 < key[2 * q + 1]) key[2 * q + 1] = k1;
            }
        }
    }

    // cross-row reduction (overlay on es: 8*256*8B = 16 KB)
    __syncthreads();
    unsigned long long* red = reinterpret_cast<unsigned long long*>(&es[0][0]);
    #pragma unroll
    for (int j = 0; j < 8; ++j) red[row * TM + 8 * col + j] = key[j];
    __syncthreads();
    {
        unsigned long long kmin = red[tid];
        #pragma unroll
        for (int r = 1; r < 8; ++r) {
            unsigned long long k2 = red[r * TM + tid];
            if (k2 < kmin) kmin = k2;
        }
        g_part[(size_t)split * NPTS + p0 + tid] = kmin;
    }
}

// ---------------------------------------------------------------------------
// Kernel 3: merge split partials -> idx output
// ---------------------------------------------------------------------------
__global__ void merge_kernel(float* __restrict__ out) {
    int p = blockIdx.x * blockDim.x + threadIdx.x;
    unsigned long long kmin = g_part[p];
    #pragma unroll
    for (int s = 1; s < NSPLIT; ++s) {
        unsigned long long k2 = g_part[(size_t)s * NPTS + p];
        if (k2 < kmin) kmin = k2;
    }
    int code = (int)(kmin & 0xFFFFFFFFULL);
    g_idx[p] = code;
    out[p]   = (float)code;
}

// ---------------------------------------------------------------------------
// Kernel 4: quant_laten gather (B, D, H, W)
// ---------------------------------------------------------------------------
__global__ void gather_kernel(const float* __restrict__ cb, float* __restrict__ out) {
    int i = blockIdx.x * blockDim.x + threadIdx.x;
    if (i < 32 * DDIM * HW) {
        int hw = i & 1023;
        int d  = (i >> 10) & 63;
        int b  = i >> 16;
        int k  = g_idx[(b << 10) | hw];
        out[NPTS + i] = cb[k * DDIM + d];
    }
}

extern "C" void kernel_launch(void* const* d_in, const int* in_sizes, int n_in,
                              void* d_out, int out_size) {
    const float* laten = (const float*)d_in[0];   // (32, 64, 32, 32) f32
    const float* cb    = (const float*)d_in[1];   // (2048, 64) f32
    float* out = (float*)d_out;                   // [32768 idx | 2097152 quant]

    const int smem = (DDIM * TM + TK * DDIM) * 4; // 80 KB
    cudaFuncSetAttribute(vq_main, cudaFuncAttributeMaxDynamicSharedMemorySize, smem);

    esq_kernel<<<KCODES / 128, 128>>>(cb);
    vq_main<<<dim3(NSPLIT, NPTS / TM), 256, smem>>>(laten, cb);
    merge_kernel<<<NPTS / 256, 256>>>(out);
    gather_kernel<<<(32 * DDIM * HW) / 256, 256>>>(cb, out);
}

// round 4
// speedup vs baseline: 1.0603x; 1.0375x over previous
#include <cuda_runtime.h>

#define DDIM   64
#define KCODES 2048
#define NPTS   32768      // 32 * 32 * 32
#define HW     1024       // 32 * 32
#define TM     256        // points per block tile
#define TK     64         // codes per smem tile
#define NSPLIT 8
#define KSPL   (KCODES / NSPLIT)   // 256 codes per split
#define NT     (KSPL / TK)         // 4 tiles per split

__device__ int                g_idx[NPTS];
__device__ float              g_esq[KCODES];
__device__ unsigned long long g_part[NSPLIT * NPTS];

// ---- f32x2 helpers (FFMA2 only reachable via PTX) ------------------------
__device__ __forceinline__ unsigned long long fma2(unsigned long long a,
                                                   unsigned long long b,
                                                   unsigned long long c) {
    unsigned long long d;
    asm("fma.rn.f32x2 %0, %1, %2, %3;" : "=l"(d) : "l"(a), "l"(b), "l"(c));
    return d;
}
__device__ __forceinline__ unsigned long long rep2(float x) {
    unsigned long long d;
    asm("mov.b64 %0, {%1, %1};" : "=l"(d) : "f"(x), "f"(x));
    return d;
}
__device__ __forceinline__ void unpack2(unsigned long long v, float& lo, float& hi) {
    asm("mov.b64 {%0, %1}, %2;" : "=f"(lo), "=f"(hi) : "l"(v));
}
__device__ __forceinline__ unsigned long long enc_key(float dist, int code) {
    unsigned int u = __float_as_uint(dist);
    u = (u & 0x80000000u) ? ~u : (u | 0x80000000u);  // total order
    return ((unsigned long long)u << 32) | (unsigned)code;
}

union F4U { float4 f; unsigned long long u[2]; };

// ---------------------------------------------------------------------------
// Kernel 1: e_sq[k] (sequential fp32 order preserved, float4 loads)
// ---------------------------------------------------------------------------
__global__ void esq_kernel(const float* __restrict__ cb) {
    int k = blockIdx.x * blockDim.x + threadIdx.x;
    if (k < KCODES) {
        const float4* r = reinterpret_cast<const float4*>(cb + (size_t)k * DDIM);
        float4 v[16];
        #pragma unroll
        for (int i = 0; i < 16; ++i) v[i] = __ldg(&r[i]);   // batch loads, MLP=16
        float s = 0.f;
        #pragma unroll
        for (int i = 0; i < 16; ++i) {                       // strict sequential order
            s = fmaf(v[i].x, v[i].x, s); s = fmaf(v[i].y, v[i].y, s);
            s = fmaf(v[i].z, v[i].z, s); s = fmaf(v[i].w, v[i].w, s);
        }
        g_esq[k] = s;
    }
}

// ---------------------------------------------------------------------------
// Kernel 2: main distance + per-split argmin.
// Grid (NSPLIT, NPTS/TM). Block 256 thr = 32 cols (8 pts) x 8 rows (8 codes).
// FFMA2 register tile 8 pts x 8 codes. 255-reg budget (1 CTA/SM), no spills.
// Double-buffered e-tile: global->reg prefetch overlaps compute, STS after.
// ---------------------------------------------------------------------------
__global__ __launch_bounds__(256, 1)
void vq_main(const float* __restrict__ laten, const float* __restrict__ cb) {
    extern __shared__ float sm[];
    float (*xs)[TM] = reinterpret_cast<float (*)[TM]>(sm);                 // 64 KB
    float* es0 = sm + DDIM * TM;                                           // 16 KB
    float* es1 = es0 + TK * DDIM;                                          // 16 KB

    const int tid   = threadIdx.x;
    const int col   = tid & 31;
    const int row   = tid >> 5;
    const int split = blockIdx.x;
    const int p0    = blockIdx.y * TM;
    const int b     = p0 >> 10;
    const int hw0   = p0 & 1023;
    const float* lat_b   = laten + (size_t)b * (DDIM * HW) + hw0;
    const float* cb_base = cb + (size_t)split * KSPL * DDIM;

    // stage x tile (float4, coalesced)
    #pragma unroll
    for (int it = 0; it < 16; ++it) {
        int f = tid + it * 256;               // 4096 float4s
        int d = f >> 6, pf = f & 63;
        float4 v = *reinterpret_cast<const float4*>(lat_b + d * HW + pf * 4);
        *reinterpret_cast<float4*>(&xs[d][pf * 4]) = v;
    }
    // stage e tile 0 directly
    {
        const float4* src = reinterpret_cast<const float4*>(cb_base);
        float4* dst = reinterpret_cast<float4*>(es0);
        #pragma unroll
        for (int it = 0; it < 4; ++it) dst[tid + it * 256] = src[tid + it * 256];
    }
    __syncthreads();

    // x_sq for my 8 points, sequential over d
    float xsq[8];
    #pragma unroll
    for (int j = 0; j < 8; ++j) xsq[j] = 0.f;
    #pragma unroll 8
    for (int d = 0; d < DDIM; ++d) {
        float4 a = *reinterpret_cast<const float4*>(&xs[d][8 * col]);
        float4 c = *reinterpret_cast<const float4*>(&xs[d][8 * col + 4]);
        xsq[0] = fmaf(a.x, a.x, xsq[0]); xsq[1] = fmaf(a.y, a.y, xsq[1]);
        xsq[2] = fmaf(a.z, a.z, xsq[2]); xsq[3] = fmaf(a.w, a.w, xsq[3]);
        xsq[4] = fmaf(c.x, c.x, xsq[4]); xsq[5] = fmaf(c.y, c.y, xsq[5]);
        xsq[6] = fmaf(c.z, c.z, xsq[6]); xsq[7] = fmaf(c.w, c.w, xsq[7]);
    }

    unsigned long long key[8];
    #pragma unroll
    for (int j = 0; j < 8; ++j) key[j] = ~0ULL;

    #pragma unroll
    for (int kt = 0; kt < NT; ++kt) {
        const float* es = (kt & 1) ? es1 : es0;
        float*       en = (kt & 1) ? es0 : es1;

        // prefetch next tile into registers (hidden behind compute below)
        float4 pf[4];
        if (kt + 1 < NT) {
            const float4* src = reinterpret_cast<const float4*>(
                cb_base + (size_t)(kt + 1) * TK * DDIM);
            #pragma unroll
            for (int it = 0; it < 4; ++it) pf[it] = __ldg(&src[tid + it * 256]);
        }

        unsigned long long acc[8][4];
        #pragma unroll
        for (int cc = 0; cc < 8; ++cc)
            #pragma unroll
            for (int q = 0; q < 4; ++q) acc[cc][q] = 0ULL;

        #pragma unroll 2
        for (int d = 0; d < DDIM; d += 2) {
            F4U A0, A1, B0, B1;
            A0.f = *reinterpret_cast<const float4*>(&xs[d][8 * col]);
            A1.f = *reinterpret_cast<const float4*>(&xs[d][8 * col + 4]);
            B0.f = *reinterpret_cast<const float4*>(&xs[d + 1][8 * col]);
            B1.f = *reinterpret_cast<const float4*>(&xs[d + 1][8 * col + 4]);
            #pragma unroll
            for (int cc = 0; cc < 8; ++cc) {
                float2 e = *reinterpret_cast<const float2*>(&es[(row * 8 + cc) * DDIM + d]);
                unsigned long long e0 = rep2(e.x);
                unsigned long long e1 = rep2(e.y);
                acc[cc][0] = fma2(A0.u[0], e0, acc[cc][0]);
                acc[cc][1] = fma2(A0.u[1], e0, acc[cc][1]);
                acc[cc][2] = fma2(A1.u[0], e0, acc[cc][2]);
                acc[cc][3] = fma2(A1.u[1], e0, acc[cc][3]);
                acc[cc][0] = fma2(B0.u[0], e1, acc[cc][0]);
                acc[cc][1] = fma2(B0.u[1], e1, acc[cc][1]);
                acc[cc][2] = fma2(B1.u[0], e1, acc[cc][2]);
                acc[cc][3] = fma2(B1.u[1], e1, acc[cc][3]);
            }
        }

        #pragma unroll
        for (int cc = 0; cc < 8; ++cc) {
            int code = split * KSPL + kt * TK + row * 8 + cc;
            float eq = __ldg(&g_esq[code]);
            #pragma unroll
            for (int q = 0; q < 4; ++q) {
                float dlo, dhi;
                unpack2(acc[cc][q], dlo, dhi);
                float dist0 = fmaf(-2.f, dlo, xsq[2 * q])     + eq;
                float dist1 = fmaf(-2.f, dhi, xsq[2 * q + 1]) + eq;
                unsigned long long k0 = enc_key(dist0, code);
                unsigned long long k1 = enc_key(dist1, code);
                if (k0 < key[2 * q])     key[2 * q]     = k0;
                if (k1 < key[2 * q + 1]) key[2 * q + 1] = k1;
            }
        }

        if (kt + 1 < NT) {
            float4* dst = reinterpret_cast<float4*>(en);
            #pragma unroll
            for (int it = 0; it < 4; ++it) dst[tid + it * 256] = pf[it];
        }
        __syncthreads();
    }

    // cross-row reduction (overlay on xs, 16 KB needed)
    unsigned long long* red = reinterpret_cast<unsigned long long*>(&xs[0][0]);
    #pragma unroll
    for (int j = 0; j < 8; ++j) red[row * TM + 8 * col + j] = key[j];
    __syncthreads();
    {
        unsigned long long kmin = red[tid];
        #pragma unroll
        for (int r = 1; r < 8; ++r) {
            unsigned long long k2 = red[r * TM + tid];
            if (k2 < kmin) kmin = k2;
        }
        g_part[(size_t)split * NPTS + p0 + tid] = kmin;
    }
}

// ---------------------------------------------------------------------------
// Kernel 3: merge split partials -> idx output
// ---------------------------------------------------------------------------
__global__ void merge_kernel(float* __restrict__ out) {
    int p = blockIdx.x * blockDim.x + threadIdx.x;
    unsigned long long kmin = g_part[p];
    #pragma unroll
    for (int s = 1; s < NSPLIT; ++s) {
        unsigned long long k2 = g_part[(size_t)s * NPTS + p];
        if (k2 < kmin) kmin = k2;
    }
    int code = (int)(kmin & 0xFFFFFFFFULL);
    g_idx[p] = code;
    out[p]   = (float)code;
}

// ---------------------------------------------------------------------------
// Kernel 4: quant_laten gather (B, D, H, W), float4 writes (4 hw / thread)
// ---------------------------------------------------------------------------
__global__ void gather_kernel(const float* __restrict__ cb, float* __restrict__ out) {
    int i = blockIdx.x * blockDim.x + threadIdx.x;     // over (b, d, hw/4)
    if (i < 32 * DDIM * (HW / 4)) {
        int hw4 = i & 255;
        int d   = (i >> 8) & 63;
        int b   = i >> 14;
        const int* idx = &g_idx[(b << 10) | (hw4 * 4)];
        int k0 = idx[0], k1 = idx[1], k2 = idx[2], k3 = idx[3];
        float4 v;
        v.x = __ldg(&cb[k0 * DDIM + d]);
        v.y = __ldg(&cb[k1 * DDIM + d]);
        v.z = __ldg(&cb[k2 * DDIM + d]);
        v.w = __ldg(&cb[k3 * DDIM + d]);
        *reinterpret_cast<float4*>(&out[NPTS + (size_t)i * 4]) = v;
    }
}

extern "C" void kernel_launch(void* const* d_in, const int* in_sizes, int n_in,
                              void* d_out, int out_size) {
    const float* laten = (const float*)d_in[0];   // (32, 64, 32, 32) f32
    const float* cb    = (const float*)d_in[1];   // (2048, 64) f32
    float* out = (float*)d_out;                   // [32768 idx | 2097152 quant]

    const int smem = (DDIM * TM + 2 * TK * DDIM) * 4;   // 96 KB
    cudaFuncSetAttribute(vq_main, cudaFuncAttributeMaxDynamicSharedMemorySize, smem);

    esq_kernel<<<KCODES / 128, 128>>>(cb);
    vq_main<<<dim3(NSPLIT, NPTS / TM), 256, smem>>>(laten, cb);
    merge_kernel<<<NPTS / 256, 256>>>(out);
    gather_kernel<<<(32 * DDIM * (HW / 4)) / 256, 256>>>(cb, out);
}